// round 16
// baseline (speedup 1.0000x reference)
#include <cuda_runtime.h>

// FullPairwise (non-PBC): output layout (float32), MP = M*P:
//   [0      , 2*MP) : atom_index12   out[r*MP + m*P + p] = (r? j : i) + m*N
//   [2*MP   , 5*MP) : shift_values   zeros
//   [5*MP   , 6*MP) : mask           1.0f if d2 <= 5.2^2 else 0.0f
// Total = 6*MP floats = 201 MB -> all offsets fit in uint32.
//
// Fused, fine-grained: grid = NM*4094 = 16,376 uniform 128-thread blocks.
// Each thread: 1 quad (4 pairs -> 3 STG.128) + 3 zero float4 (3 STG.128).
// Exact splits (no guards): QUADS/mol = 4094*128, ZERO_F4 = 16376*384.
static constexpr int      NA = 2048;
static constexpr int      NM = 4;
static constexpr unsigned PP = (unsigned)NA * (NA - 1) / 2;   // 2,096,128
static constexpr unsigned MP = (unsigned)NM * PP;             // 8,384,512

static constexpr int      THREADS     = 128;
static constexpr int      PAIR_BLOCKS = 4094;                 // per molecule (exact)
static constexpr int      GRID        = NM * PAIR_BLOCKS;     // 16,376
static constexpr unsigned ZERO_F4     = 3 * MP / 4;           // 6,288,384 = 16376*384

__device__ __forceinline__ int cumrow(int i) {
    return i * (NA - 1) - ((i * (i - 1)) >> 1);
}

__global__ void __launch_bounds__(128)
fullpair_kernel(const float* __restrict__ coords,   // [NM, NA, 3] AoS
                float* __restrict__ out)
{
    const unsigned bid = blockIdx.x;                  // 0 .. 16375

    // ---- pair share first: get coordinate loads in flight early ----
    const unsigned m  = bid / (unsigned)PAIR_BLOCKS;
    const unsigned pb = bid - m * PAIR_BLOCKS;
    const unsigned p0 = (pb * THREADS + threadIdx.x) * 4u;   // < PP (exact split)

    // fp32 triangular inversion (operands < 2^24, exact), exact int correction
    float disc = (float)(16769025u - 8u * p0);        // 4095^2 - 8p
    int i = (int)((4095.0f - sqrtf(disc)) * 0.5f);
    if (i < 0) i = 0;
    if (i > NA - 2) i = NA - 2;
    while (cumrow(i + 1) <= (int)p0) ++i;
    while (cumrow(i) > (int)p0) --i;
    int j = (int)p0 - cumrow(i) + i + 1;

    const float c2  = 5.2f * 5.2f;
    const float off = (float)(m * NA);
    const float* __restrict__ cm = coords + m * (NA * 3);

    float iv[4], jv[4], mk[4];
    float cix = 0.f, ciy = 0.f, ciz = 0.f;
    int cached_i = -1;
    int ii = i, jj = j;
    #pragma unroll
    for (int k = 0; k < 4; ++k) {
        iv[k] = (float)ii + off;
        jv[k] = (float)jj + off;
        if (ii != cached_i) {
            const float* ci = cm + ii * 3;
            cix = ci[0]; ciy = ci[1]; ciz = ci[2];
            cached_i = ii;
        }
        const float* cj = cm + jj * 3;
        float dx = __fsub_rn(cix, cj[0]);
        float dy = __fsub_rn(ciy, cj[1]);
        float dz = __fsub_rn(ciz, cj[2]);
        // same association order as jnp.sum axis -1: (x+y)+z, no fma
        float d2 = __fadd_rn(__fadd_rn(__fmul_rn(dx, dx), __fmul_rn(dy, dy)),
                             __fmul_rn(dz, dz));
        mk[k] = (d2 <= c2) ? 1.0f : 0.0f;
        ++jj;
        if (jj >= NA) { ++ii; jj = ii + 1; }
    }

    const unsigned base_i = m * PP + p0;                 // index row 0
    const unsigned base_j = base_i + MP;                 // index row 1
    const unsigned base_k = base_i + 5u * MP;            // mask

    __stcs((float4*)(out + base_i), make_float4(iv[0], iv[1], iv[2], iv[3]));
    __stcs((float4*)(out + base_j), make_float4(jv[0], jv[1], jv[2], jv[3]));
    __stcs((float4*)(out + base_k), make_float4(mk[0], mk[1], mk[2], mk[3]));

    // ---- zero share last (no deps): block writes f4 span [bid*384, +384) ----
    {
        const unsigned zbase = bid * 384u;
        float4* zp = (float4*)(out + 2u * MP);
        const float4 z = make_float4(0.f, 0.f, 0.f, 0.f);
        #pragma unroll
        for (int k = 0; k < 3; ++k)
            __stcs(zp + zbase + (unsigned)k * THREADS + threadIdx.x, z);
    }
}

extern "C" void kernel_launch(void* const* d_in, const int* in_sizes, int n_in,
                              void* d_out, int out_size) {
    // inputs per metadata order: species(int32), coordinates(f32), cell(f32), pbc(bool)
    const float* coords = (const float*)d_in[1];
    float* out = (float*)d_out;

    fullpair_kernel<<<GRID, THREADS>>>(coords, out);
}